// round 3
// baseline (speedup 1.0000x reference)
#include <cuda_runtime.h>
#include <cstdint>

// ---------------- problem dims ----------------
#define MDIM 16384   // B*S
#define NDIM 1024    // DM
#define KDIM 1024    // DM
#define WSZ  ((size_t)NDIM * KDIM)

// ---------------- GEMM tiling ----------------
#define BM 128
#define BN 128
#define BK 32
#define NT (KDIM / BK)          // 32 k-tiles
#define STAGE_BYTES 16384       // A or B stage: 128x32 tf32 = 16KB
#define GEMM_SMEM (6 * STAGE_BYTES)   // 3 stages x (A+B) = 96KB

// ---------------- scratch (no allocs allowed) ----------------
__device__ float    g_q[(size_t)MDIM * NDIM];
__device__ float    g_k[(size_t)MDIM * NDIM];
__device__ float    g_v[(size_t)MDIM * NDIM];
__device__ float    g_attn[(size_t)MDIM * NDIM];
__device__ unsigned g_wt[4ull * NDIM * KDIM];   // 4 packed tf32 weight matrices

// ---------------- helpers ----------------
__device__ __forceinline__ unsigned f2tf(float x) {
    unsigned r;
    asm("cvt.rna.tf32.f32 %0, %1;" : "=r"(r) : "f"(x));
    return r;
}

__device__ __forceinline__ uint32_t smem_u32(const void* p) {
    uint32_t a;
    asm("{ .reg .u64 t; cvta.to.shared.u64 t, %1; cvt.u32.u64 %0, t; }" : "=r"(a) : "l"(p));
    return a;
}

__device__ __forceinline__ void cp_async16(uint32_t saddr, const void* gaddr) {
    asm volatile("cp.async.cg.shared.global [%0], [%1], 16;\n" :: "r"(saddr), "l"(gaddr));
}

__device__ __forceinline__ void lds128(uint32_t& a, uint32_t& b, uint32_t& c, uint32_t& d,
                                       uint32_t addr) {
    asm volatile("ld.shared.v4.b32 {%0,%1,%2,%3}, [%4];"
                 : "=r"(a), "=r"(b), "=r"(c), "=r"(d) : "r"(addr));
}

__device__ __forceinline__ void sts128(uint32_t addr, uint32_t a, uint32_t b,
                                       uint32_t c, uint32_t d) {
    asm volatile("st.shared.v4.b32 [%0], {%1,%2,%3,%4};"
                 :: "r"(addr), "r"(a), "r"(b), "r"(c), "r"(d));
}

__device__ __forceinline__ void mma_tf32(float c[4], const uint32_t a[4], uint32_t b0, uint32_t b1) {
    asm volatile(
        "mma.sync.aligned.m16n8k8.row.col.f32.tf32.tf32.f32 "
        "{%0,%1,%2,%3}, {%4,%5,%6,%7}, {%8,%9}, {%0,%1,%2,%3};\n"
        : "+f"(c[0]), "+f"(c[1]), "+f"(c[2]), "+f"(c[3])
        : "r"(a[0]), "r"(a[1]), "r"(a[2]), "r"(a[3]), "r"(b0), "r"(b1));
}

// ---------------- weight prep: pack W[k][n] -> fragment-major tf32 ----------------
// Per (nblk in 0..7, kt in 0..31): a contiguous 16KB chunk laid out as
//   float4 slot (h = g16*32 + ks*8 + grp, tig), words {B[k][c], B[k][c+8], B[k+4][c], B[k+4][c+8]}
//   with c = g16*16+grp (col&8 -> word +1), k = ks*8+tig (k&4 -> word +2).
__global__ void prep_w(const float* __restrict__ W0, const float* __restrict__ W1,
                       const float* __restrict__ W2, const float* __restrict__ W3,
                       unsigned* __restrict__ out)
{
    const int k = blockIdx.x;                 // 0..1023
    const int z = blockIdx.z;                 // matrix select
    const float* W = (z == 0) ? W0 : (z == 1) ? W1 : (z == 2) ? W2 : W3;
    unsigned* O = out + (size_t)z * WSZ;

    const int kt = k >> 5, kin = k & 31;
    const int ks = kin >> 3, tig = kin & 3, kh = (kin >> 2) & 1;

    const int nb = threadIdx.x * 4;           // 4 consecutive n per thread
    float4 v = *(const float4*)&W[(size_t)k * NDIM + nb];
    float vv[4] = {v.x, v.y, v.z, v.w};
#pragma unroll
    for (int j = 0; j < 4; j++) {
        int n = nb + j;
        int nblk = n >> 7, col = n & 127;
        int g16 = col >> 4, grp = col & 7, hb = (col >> 3) & 1;
        int fidx = ((nblk * 32 + kt) * 1024 + ((g16 * 32 + ks * 8 + grp) * 4 + tig)) * 4
                 + hb + 2 * kh;
        O[fidx] = f2tf(vv[j]);
    }
}

// ---------------- GEMM core (device-side, shared by both kernels) ----------------
// C[M,N] = A[M,K] @ Wt_packed^T + bias.  128x128 block, 4 warps (2x2) of 64x64.
struct GemmArgs {
    const float* A;
    const unsigned* Bt;      // packed chunks base for this matrix
    const float* bias;
    float* C;
    float* C2;
};

__device__ __forceinline__ void ldgA(const float* __restrict__ A, int m0, int kt, int g,
                                     float4 v[4])
{
    const int r = (g >> 5) * 16 + (g & 7);
    const int k = kt * BK + ((g >> 3) & 3) * 8;
    const float* p = A + (size_t)(m0 + r) * KDIM + k;
    v[0] = *(const float4*)p;                      // (r,   k..k+3)
    v[1] = *(const float4*)(p + 4);                // (r,   k+4..)
    v[2] = *(const float4*)(p + 8 * KDIM);         // (r+8, k..)
    v[3] = *(const float4*)(p + 8 * KDIM + 4);     // (r+8, k+4..)
}

__device__ __forceinline__ void stsA(uint32_t slotbase, int g, const float4 v[4])
{
    const float* a0 = (const float*)&v[0];
    const float* a1 = (const float*)&v[1];
    const float* b0 = (const float*)&v[2];
    const float* b1 = (const float*)&v[3];
    const uint32_t base = slotbase + g * 64;
#pragma unroll
    for (int tig = 0; tig < 4; tig++)
        sts128(base + tig * 16, f2tf(a0[tig]), f2tf(b0[tig]), f2tf(a1[tig]), f2tf(b1[tig]));
}

__device__ __forceinline__ void gemm_body(const GemmArgs& ga, uint32_t sb)
{
    const int tid = threadIdx.x;               // 128 threads
    const int wid = tid >> 5, lane = tid & 31;
    const int grp = lane >> 2, tig = lane & 3;
    const int warp_m = wid >> 1, warp_n = wid & 1;
    const int wm = warp_m * 64, wn = warp_n * 64;
    const int m0 = blockIdx.y * BM;
    const int nblk = blockIdx.x;
    const int g0 = tid, g1 = tid + 128;

    const char* bsrc = (const char*)ga.Bt + (size_t)nblk * NT * STAGE_BYTES;

    float acc[4][8][4];
#pragma unroll
    for (int mi = 0; mi < 4; mi++)
#pragma unroll
        for (int ni = 0; ni < 8; ni++)
#pragma unroll
            for (int r = 0; r < 4; r++) acc[mi][ni][r] = 0.f;

    auto cpB = [&](int kt, int slot) {
        const char* src = bsrc + (size_t)kt * STAGE_BYTES + tid * 128;
        uint32_t dst = sb + 3 * STAGE_BYTES + slot * STAGE_BYTES + tid * 128;
#pragma unroll
        for (int i = 0; i < 8; i++) cp_async16(dst + i * 16, src + i * 16);
        asm volatile("cp.async.commit_group;\n");
    };

    // ---- prologue: tiles 0 and 1 ----
    float4 p0a[4], p0b[4], p1a[4], p1b[4];
    ldgA(ga.A, m0, 0, g0, p0a); ldgA(ga.A, m0, 0, g1, p0b);
    ldgA(ga.A, m0, 1, g0, p1a); ldgA(ga.A, m0, 1, g1, p1b);
    cpB(0, 0);
    cpB(1, 1);
    stsA(sb + 0 * STAGE_BYTES, g0, p0a); stsA(sb + 0 * STAGE_BYTES, g1, p0b);
    stsA(sb + 1 * STAGE_BYTES, g0, p1a); stsA(sb + 1 * STAGE_BYTES, g1, p1b);
    float4 pra[4], prb[4];
    ldgA(ga.A, m0, 2, g0, pra); ldgA(ga.A, m0, 2, g1, prb);

    const uint32_t aOff = wm * 128 /*(wm/16)*2048*/ + grp * 64 + tig * 16;
    const uint32_t bOff = 3 * STAGE_BYTES + wn * 128 + grp * 64 + tig * 16;

    int slot = 0;
    for (int kt = 0; kt < NT; kt++) {
        if (kt < NT - 1) asm volatile("cp.async.wait_group 1;\n");
        else             asm volatile("cp.async.wait_group 0;\n");
        __syncthreads();

        if (kt + 2 < NT) {
            int sl2 = slot + 2; if (sl2 >= 3) sl2 -= 3;
            stsA(sb + sl2 * STAGE_BYTES, g0, pra);
            stsA(sb + sl2 * STAGE_BYTES, g1, prb);
            cpB(kt + 2, sl2);
        }
        if (kt + 3 < NT) {
            ldgA(ga.A, m0, kt + 3, g0, pra);
            ldgA(ga.A, m0, kt + 3, g1, prb);
        }

        const uint32_t aBase = sb + slot * STAGE_BYTES + aOff;
        const uint32_t bBase = sb + slot * STAGE_BYTES + bOff;
#pragma unroll
        for (int ks = 0; ks < 4; ks++) {
            uint32_t a4[4][4], b4[4][4];
#pragma unroll
            for (int mi = 0; mi < 4; mi++)
                lds128(a4[mi][0], a4[mi][1], a4[mi][2], a4[mi][3],
                       aBase + mi * 2048 + ks * 512);
#pragma unroll
            for (int np = 0; np < 4; np++)
                lds128(b4[np][0], b4[np][1], b4[np][2], b4[np][3],
                       bBase + np * 2048 + ks * 512);
#pragma unroll
            for (int mi = 0; mi < 4; mi++) {
#pragma unroll
                for (int np = 0; np < 4; np++) {
                    mma_tf32(acc[mi][2 * np + 0], a4[mi], b4[np][0], b4[np][2]);
                    mma_tf32(acc[mi][2 * np + 1], a4[mi], b4[np][1], b4[np][3]);
                }
            }
        }
        slot++; if (slot >= 3) slot -= 3;
    }

    // ---- epilogue: +bias, store (optionally duplicated) ----
    const int n0 = nblk * BN;
#pragma unroll
    for (int mi = 0; mi < 4; mi++) {
        const int r0 = m0 + wm + mi * 16 + grp;
#pragma unroll
        for (int ni = 0; ni < 8; ni++) {
            const int col = n0 + wn + ni * 8 + tig * 2;
            float2 bv = *(const float2*)&ga.bias[col];
            float2 lo = make_float2(acc[mi][ni][0] + bv.x, acc[mi][ni][1] + bv.y);
            float2 hi = make_float2(acc[mi][ni][2] + bv.x, acc[mi][ni][3] + bv.y);
            *(float2*)&ga.C[(size_t)r0 * NDIM + col] = lo;
            *(float2*)&ga.C[(size_t)(r0 + 8) * NDIM + col] = hi;
            if (ga.C2) {
                *(float2*)&ga.C2[(size_t)r0 * NDIM + col] = lo;
                *(float2*)&ga.C2[(size_t)(r0 + 8) * NDIM + col] = hi;
            }
        }
    }
}

// fused QKV projections: grid.z selects which of the three GEMMs
__global__ void __launch_bounds__(128, 2) gemm_qkv(
    const float* __restrict__ Aq, const float* __restrict__ Ak, const float* __restrict__ Av,
    const unsigned* __restrict__ BtBase,
    const float* __restrict__ bq, const float* __restrict__ bk, const float* __restrict__ bv,
    float* __restrict__ Cq, float* __restrict__ Ck, float* __restrict__ Cv)
{
    extern __shared__ char smem[];
    const int z = blockIdx.z;
    GemmArgs ga;
    ga.A    = (z == 0) ? Aq : (z == 1) ? Ak : Av;
    ga.Bt   = BtBase + (size_t)z * WSZ;
    ga.bias = (z == 0) ? bq : (z == 1) ? bk : bv;
    ga.C    = (z == 0) ? Cq : (z == 1) ? Ck : Cv;
    ga.C2   = nullptr;
    gemm_body(ga, smem_u32(smem));
}

__global__ void __launch_bounds__(128, 2) gemm_out(
    const float* __restrict__ A, const unsigned* __restrict__ Bt,
    const float* __restrict__ bias, float* __restrict__ C, float* __restrict__ C2)
{
    extern __shared__ char smem[];
    GemmArgs ga{A, Bt, bias, C, C2};
    gemm_body(ga, smem_u32(smem));
}

// ---------------- per-token head-axis attention (unchanged, known-good) ----------------
#define AT_WARPS 2
#define ROWP 68
#define WSTRIDE (3 * 16 * ROWP + 16 * 17)

__global__ void attn_kernel(const float* __restrict__ qg, const float* __restrict__ kg,
                            const float* __restrict__ vg, const float* __restrict__ mg,
                            float* __restrict__ outg)
{
    __shared__ float sm[AT_WARPS * WSTRIDE];
    const int warp = threadIdx.x >> 5, lane = threadIdx.x & 31;
    const int tok = blockIdx.x * AT_WARPS + warp;
    float* sq = sm + warp * WSTRIDE;
    float* sk = sq + 16 * ROWP;
    float* sv = sk + 16 * ROWP;
    float* sw = sv + 16 * ROWP;
    const size_t base = (size_t)tok * 1024;

#pragma unroll
    for (int i = 0; i < 8; i++) {
        int idx = lane + i * 32;
        int row = idx >> 4, col = (idx & 15) * 4;
        *(float4*)&sq[row * ROWP + col] = *(const float4*)&qg[base + row * 64 + col];
        *(float4*)&sk[row * ROWP + col] = *(const float4*)&kg[base + row * 64 + col];
        *(float4*)&sv[row * ROWP + col] = *(const float4*)&vg[base + row * 64 + col];
    }
    __syncwarp();

    const int h = lane >> 1, gs = (lane & 1) * 8;
    float s[8];
#pragma unroll
    for (int gi = 0; gi < 8; gi++) s[gi] = 0.f;

#pragma unroll
    for (int dc = 0; dc < 4; dc++) {
        const float* qp = &sq[h * ROWP + dc * 16];
        float4 q0 = *(const float4*)(qp + 0);
        float4 q1 = *(const float4*)(qp + 4);
        float4 q2 = *(const float4*)(qp + 8);
        float4 q3 = *(const float4*)(qp + 12);
#pragma unroll
        for (int gi = 0; gi < 8; gi++) {
            const float* kp = &sk[(gs + gi) * ROWP + dc * 16];
            float4 k0 = *(const float4*)(kp + 0);
            float4 k1 = *(const float4*)(kp + 4);
            float4 k2 = *(const float4*)(kp + 8);
            float4 k3 = *(const float4*)(kp + 12);
            s[gi] += q0.x * k0.x + q0.y * k0.y + q0.z * k0.z + q0.w * k0.w
                   + q1.x * k1.x + q1.y * k1.y + q1.z * k1.z + q1.w * k1.w
                   + q2.x * k2.x + q2.y * k2.y + q2.z * k2.z + q2.w * k2.w
                   + q3.x * k3.x + q3.y * k3.y + q3.z * k3.z + q3.w * k3.w;
        }
    }

    const float* mp = mg + (size_t)tok * 256 + h * 16 + gs;
    float mx = -1e30f;
#pragma unroll
    for (int gi = 0; gi < 8; gi++) {
        s[gi] = s[gi] * 0.125f - 1e9f * mp[gi];
        mx = fmaxf(mx, s[gi]);
    }
    mx = fmaxf(mx, __shfl_xor_sync(0xffffffffu, mx, 1));
    float sum = 0.f;
#pragma unroll
    for (int gi = 0; gi < 8; gi++) { s[gi] = expf(s[gi] - mx); sum += s[gi]; }
    sum += __shfl_xor_sync(0xffffffffu, sum, 1);
    const float inv = 1.0f / sum;
#pragma unroll
    for (int gi = 0; gi < 8; gi++) sw[h * 17 + gs + gi] = s[gi] * inv;
    __syncwarp();

    const int dh = (lane & 1) * 32;
    float4 o[8];
#pragma unroll
    for (int j = 0; j < 8; j++) o[j] = make_float4(0.f, 0.f, 0.f, 0.f);
#pragma unroll
    for (int g = 0; g < 16; g++) {
        const float w = sw[h * 17 + g];
        const float* vp = &sv[g * ROWP + dh];
#pragma unroll
        for (int j = 0; j < 8; j++) {
            float4 vv = *(const float4*)&vp[j * 4];
            o[j].x += w * vv.x; o[j].y += w * vv.y;
            o[j].z += w * vv.z; o[j].w += w * vv.w;
        }
    }
    __syncwarp();

#pragma unroll
    for (int j = 0; j < 8; j++) *(float4*)&sq[h * 64 + dh + j * 4] = o[j];
    __syncwarp();
    float* op = outg + base;
#pragma unroll
    for (int i = 0; i < 8; i++) {
        int idx = lane + i * 32;
        *(float4*)&op[idx * 4] = *(const float4*)&sq[idx * 4];
    }
}

// ---------------- launch ----------------
extern "C" void kernel_launch(void* const* d_in, const int* in_sizes, int n_in,
                              void* d_out, int out_size)
{
    const float* Q  = (const float*)d_in[0];
    const float* K  = (const float*)d_in[1];
    const float* V  = (const float*)d_in[2];
    const float* Msk= (const float*)d_in[3];
    const float* Wq = (const float*)d_in[4];
    const float* bq = (const float*)d_in[5];
    const float* Wk = (const float*)d_in[6];
    const float* bk = (const float*)d_in[7];
    const float* Wv = (const float*)d_in[8];
    const float* bv = (const float*)d_in[9];
    const float* Wo = (const float*)d_in[10];
    const float* bo = (const float*)d_in[11];
    float* out = (float*)d_out;

    float *gq, *gk, *gv, *ga;
    unsigned* wt;
    cudaGetSymbolAddress((void**)&gq, g_q);
    cudaGetSymbolAddress((void**)&gk, g_k);
    cudaGetSymbolAddress((void**)&gv, g_v);
    cudaGetSymbolAddress((void**)&ga, g_attn);
    cudaGetSymbolAddress((void**)&wt, g_wt);

    cudaFuncSetAttribute(gemm_qkv, cudaFuncAttributeMaxDynamicSharedMemorySize, GEMM_SMEM);
    cudaFuncSetAttribute(gemm_out, cudaFuncAttributeMaxDynamicSharedMemorySize, GEMM_SMEM);

    prep_w<<<dim3(KDIM, 1, 4), 256>>>(Wq, Wk, Wv, Wo, wt);

    dim3 gqkv(NDIM / BN, MDIM / BM, 3);   // (8, 128, 3)
    gemm_qkv<<<gqkv, 128, GEMM_SMEM>>>(Q, K, V, wt, bq, bk, bv, gq, gk, gv);

    attn_kernel<<<MDIM / AT_WARPS, AT_WARPS * 32>>>(gq, gk, gv, Msk, ga);

    float* out2 = ((long long)out_size >= 2LL * MDIM * NDIM) ? out + (size_t)MDIM * NDIM
                                                             : nullptr;
    dim3 go(NDIM / BN, MDIM / BM);
    gemm_out<<<go, 128, GEMM_SMEM>>>(ga, wt + 3 * WSZ, bo, out, out2);
}

// round 4
// speedup vs baseline: 2.2069x; 2.2069x over previous
#include <cuda_runtime.h>
#include <cuda_fp16.h>
#include <cstdint>

// ---------------- problem dims ----------------
#define MDIM 16384   // B*S
#define NDIM 1024    // DM
#define KDIM 1024    // DM

// ---------------- GEMM tiling ----------------
#define BM 128
#define BN 128
#define BK 64
#define NT (KDIM / BK)              // 16 k-stages
#define A_STAGE 16384               // 128x64 fp16
#define B_STAGE 16384               // 128x64 fp16
#define STAGE_BYTES (A_STAGE + B_STAGE)   // 32KB
#define GEMM_SMEM (3 * STAGE_BYTES)       // 96KB

// packed sizes (uint4 units)
#define ACT_CHUNKS ((MDIM / 128) * NT)    // 128*16 chunks per activation matrix
#define W_CHUNKS   ((NDIM / 128) * NT)    // 8*16 per weight matrix
#define CHUNK_U4   1024                   // 16KB per chunk
#define ACT_PACK_U4 ((size_t)ACT_CHUNKS * CHUNK_U4)
#define W_PACK_U4   ((size_t)W_CHUNKS * CHUNK_U4)

// ---------------- scratch (no allocs allowed) ----------------
__device__ float g_q[(size_t)MDIM * NDIM];
__device__ float g_k[(size_t)MDIM * NDIM];
__device__ float g_v[(size_t)MDIM * NDIM];
__device__ float g_attn[(size_t)MDIM * NDIM];
__device__ float g_wtf[4ull * NDIM * KDIM];            // f32 transposed weights
__device__ uint4 g_wp[4ull * W_PACK_U4];               // packed fp16 weights
__device__ uint4 g_qp[ACT_PACK_U4];
__device__ uint4 g_kp[ACT_PACK_U4];
__device__ uint4 g_vp[ACT_PACK_U4];
__device__ uint4 g_ap[ACT_PACK_U4];                    // packed attn output

// ---------------- helpers ----------------
__device__ __forceinline__ uint32_t smem_u32(const void* p) {
    uint32_t a;
    asm("{ .reg .u64 t; cvta.to.shared.u64 t, %1; cvt.u32.u64 %0, t; }" : "=r"(a) : "l"(p));
    return a;
}

__device__ __forceinline__ void cp_async16(uint32_t saddr, const void* gaddr) {
    asm volatile("cp.async.cg.shared.global [%0], [%1], 16;\n" :: "r"(saddr), "l"(gaddr));
}

__device__ __forceinline__ void lds128(uint32_t& a, uint32_t& b, uint32_t& c, uint32_t& d,
                                       uint32_t addr) {
    asm volatile("ld.shared.v4.b32 {%0,%1,%2,%3}, [%4];"
                 : "=r"(a), "=r"(b), "=r"(c), "=r"(d) : "r"(addr));
}

__device__ __forceinline__ void mma_f16(float c[4], const uint32_t a[4],
                                        uint32_t b0, uint32_t b1) {
    asm volatile(
        "mma.sync.aligned.m16n8k16.row.col.f32.f16.f16.f32 "
        "{%0,%1,%2,%3}, {%4,%5,%6,%7}, {%8,%9}, {%0,%1,%2,%3};\n"
        : "+f"(c[0]), "+f"(c[1]), "+f"(c[2]), "+f"(c[3])
        : "r"(a[0]), "r"(a[1]), "r"(a[2]), "r"(a[3]), "r"(b0), "r"(b1));
}

__device__ __forceinline__ uint32_t ph2(float lo, float hi) {
    __half2 h = __floats2half2_rn(lo, hi);
    return *reinterpret_cast<uint32_t*>(&h);
}

// ---------------- weight transpose: Wt[n][k] = W[k][n] ----------------
__global__ void wtrans(const float* __restrict__ W0, const float* __restrict__ W1,
                       const float* __restrict__ W2, const float* __restrict__ W3,
                       float* __restrict__ out)
{
    __shared__ float t[32][33];
    const float* W = (blockIdx.z == 0) ? W0 : (blockIdx.z == 1) ? W1
                   : (blockIdx.z == 2) ? W2 : W3;
    float* O = out + (size_t)blockIdx.z * NDIM * KDIM;
    const int n0 = blockIdx.x * 32, k0 = blockIdx.y * 32;
    const int tx = threadIdx.x, ty = threadIdx.y;   // 32 x 8
#pragma unroll
    for (int i = 0; i < 4; i++)
        t[ty + 8 * i][tx] = W[(size_t)(k0 + ty + 8 * i) * NDIM + n0 + tx];
    __syncthreads();
#pragma unroll
    for (int i = 0; i < 4; i++)
        O[(size_t)(n0 + ty + 8 * i) * KDIM + k0 + tx] = t[tx][ty + 8 * i];
}

// ---------------- fragment pack: f32 row-major [R x 1024] -> fp16 mma frags ----------
// chunk (mblk, kt): 128 rows x 64 k, 16KB. Within chunk: [kstep(4)][b(8)][lane(32)] x 16B
// slot words: {X[r][k..k+1], X[r+8][k..k+1], X[r][k+8..k+9], X[r+8][k+8..k+9]} fp16x2
// with r = b*16 + grp, k = kstep*16 + 2*tig, (grp,tig) = (lane>>2, lane&3).
__device__ __forceinline__ void apack_body(const float* __restrict__ src,
                                           uint4* __restrict__ dst)
{
    __shared__ float s[128 * 68];
    const int t = threadIdx.x;                 // 256
    const int mblk = blockIdx.y, kt = blockIdx.x;
#pragma unroll
    for (int i = 0; i < 8; i++) {
        int idx = t + i * 256;
        int row = idx >> 4, c4 = (idx & 15) * 4;
        *(float4*)&s[row * 68 + c4] =
            *(const float4*)&src[(size_t)(mblk * 128 + row) * KDIM + kt * 64 + c4];
    }
    __syncthreads();
    const int b = t >> 5, l = t & 31, grp = l >> 2, tig = l & 3;
    const int r0 = (b * 16 + grp) * 68, r1 = r0 + 8 * 68;
    uint4* base = dst + ((size_t)(mblk * NT + kt)) * CHUNK_U4 + b * 32 + l;
#pragma unroll
    for (int ks = 0; ks < 4; ks++) {
        const int c = ks * 16 + 2 * tig;
        float2 x0 = *(const float2*)&s[r0 + c];
        float2 x1 = *(const float2*)&s[r1 + c];
        float2 x2 = *(const float2*)&s[r0 + c + 8];
        float2 x3 = *(const float2*)&s[r1 + c + 8];
        uint4 o;
        o.x = ph2(x0.x, x0.y);
        o.y = ph2(x1.x, x1.y);
        o.z = ph2(x2.x, x2.y);
        o.w = ph2(x3.x, x3.y);
        base[ks * 256] = o;
    }
}

__global__ void apack_qkv(const float* __restrict__ Q, const float* __restrict__ K,
                          const float* __restrict__ V)
{
    const int z = blockIdx.z;
    apack_body(z == 0 ? Q : z == 1 ? K : V,
               z == 0 ? g_qp : z == 1 ? g_kp : g_vp);
}

__global__ void apack_w()
{
    const int z = blockIdx.z;
    apack_body(g_wtf + (size_t)z * NDIM * KDIM, g_wp + (size_t)z * W_PACK_U4);
}

__global__ void apack_attn(const float* __restrict__ A) { apack_body(A, g_ap); }

// ---------------- fp16 tensor-core GEMM (all operands pre-packed) ----------------
// C[M,N] = A @ Wt^T + bias. 128x128 CTA tile, 8 warps (2x4), warp tile 64x32.
__device__ __forceinline__ void gemm_body(const uint4* __restrict__ Ap,
                                          const uint4* __restrict__ Bp,
                                          const float* __restrict__ bias,
                                          float* __restrict__ C, float* __restrict__ C2,
                                          uint32_t sb)
{
    const int tid = threadIdx.x;               // 256
    const int wid = tid >> 5, lane = tid & 31;
    const int grp = lane >> 2, tig = lane & 3;
    const int warp_m = wid >> 2, warp_n = wid & 3;
    const int mblk = blockIdx.y, nblk = blockIdx.x;

    float acc[4][4][4];
#pragma unroll
    for (int mi = 0; mi < 4; mi++)
#pragma unroll
        for (int ni = 0; ni < 4; ni++)
#pragma unroll
            for (int r = 0; r < 4; r++) acc[mi][ni][r] = 0.f;

    const uint4* Abase = Ap + (size_t)mblk * NT * CHUNK_U4 + tid * 4;
    const uint4* Bbase = Bp + (size_t)nblk * NT * CHUNK_U4 + tid * 4;

    auto stage_in = [&](int kt, int slot) {
        const uint32_t da = sb + slot * STAGE_BYTES + tid * 64;
        const uint32_t db = da + A_STAGE;
        const uint4* sa = Abase + (size_t)kt * CHUNK_U4;
        const uint4* sbp = Bbase + (size_t)kt * CHUNK_U4;
#pragma unroll
        for (int i = 0; i < 4; i++) cp_async16(da + i * 16, sa + i);
#pragma unroll
        for (int i = 0; i < 4; i++) cp_async16(db + i * 16, sbp + i);
        asm volatile("cp.async.commit_group;\n");
    };

    stage_in(0, 0);
    stage_in(1, 1);

    const uint32_t aOff = warp_m * 2048 + lane * 16;
    const uint32_t bOff = A_STAGE + warp_n * 1024 + lane * 16;

    int slot = 0;
    for (int kt = 0; kt < NT; kt++) {
        if (kt < NT - 1) asm volatile("cp.async.wait_group 1;\n");
        else             asm volatile("cp.async.wait_group 0;\n");
        __syncthreads();

        if (kt + 2 < NT) {
            int sl2 = slot + 2; if (sl2 >= 3) sl2 -= 3;
            stage_in(kt + 2, sl2);
        }

        const uint32_t aBase = sb + slot * STAGE_BYTES + aOff;
        const uint32_t bBase = sb + slot * STAGE_BYTES + bOff;
#pragma unroll
        for (int ks = 0; ks < 4; ks++) {
            uint32_t a4[4][4], b4[2][4];
#pragma unroll
            for (int mi = 0; mi < 4; mi++)
                lds128(a4[mi][0], a4[mi][1], a4[mi][2], a4[mi][3],
                       aBase + ks * 4096 + mi * 512);
#pragma unroll
            for (int np = 0; np < 2; np++)
                lds128(b4[np][0], b4[np][1], b4[np][2], b4[np][3],
                       bBase + ks * 4096 + np * 512);
#pragma unroll
            for (int mi = 0; mi < 4; mi++) {
#pragma unroll
                for (int np = 0; np < 2; np++) {
                    mma_f16(acc[mi][np * 2 + 0], a4[mi], b4[np][0], b4[np][2]);
                    mma_f16(acc[mi][np * 2 + 1], a4[mi], b4[np][1], b4[np][3]);
                }
            }
        }
        slot++; if (slot >= 3) slot -= 3;
        __syncthreads();
    }

    // ---- epilogue: +bias, store (optionally duplicated) ----
    const int n0 = nblk * BN + warp_n * 32;
    const int m0 = mblk * BM + warp_m * 64;
#pragma unroll
    for (int mi = 0; mi < 4; mi++) {
        const int r0 = m0 + mi * 16 + grp;
#pragma unroll
        for (int ni = 0; ni < 4; ni++) {
            const int col = n0 + (ni >> 1) * 16 + (ni & 1) * 8 + tig * 2;
            float2 bv = *(const float2*)&bias[col];
            float2 lo = make_float2(acc[mi][ni][0] + bv.x, acc[mi][ni][1] + bv.y);
            float2 hi = make_float2(acc[mi][ni][2] + bv.x, acc[mi][ni][3] + bv.y);
            *(float2*)&C[(size_t)r0 * NDIM + col] = lo;
            *(float2*)&C[(size_t)(r0 + 8) * NDIM + col] = hi;
            if (C2) {
                *(float2*)&C2[(size_t)r0 * NDIM + col] = lo;
                *(float2*)&C2[(size_t)(r0 + 8) * NDIM + col] = hi;
            }
        }
    }
}

__global__ void __launch_bounds__(256, 2) gemm_qkv(
    const float* __restrict__ bq, const float* __restrict__ bk, const float* __restrict__ bv,
    float* __restrict__ Cq, float* __restrict__ Ck, float* __restrict__ Cv)
{
    extern __shared__ char smem[];
    const int z = blockIdx.z;
    gemm_body(z == 0 ? g_qp : z == 1 ? g_kp : g_vp,
              g_wp + (size_t)z * W_PACK_U4,
              z == 0 ? bq : z == 1 ? bk : bv,
              z == 0 ? Cq : z == 1 ? Ck : Cv, nullptr, smem_u32(smem));
}

__global__ void __launch_bounds__(256, 2) gemm_out(
    const float* __restrict__ bias, float* __restrict__ C, float* __restrict__ C2)
{
    extern __shared__ char smem[];
    gemm_body(g_ap, g_wp + 3ull * W_PACK_U4, bias, C, C2, smem_u32(smem));
}

// ---------------- per-token head-axis attention (unchanged, known-good) ----------------
#define AT_WARPS 2
#define ROWP 68
#define WSTRIDE (3 * 16 * ROWP + 16 * 17)

__global__ void attn_kernel(const float* __restrict__ qg, const float* __restrict__ kg,
                            const float* __restrict__ vg, const float* __restrict__ mg,
                            float* __restrict__ outg)
{
    __shared__ float sm[AT_WARPS * WSTRIDE];
    const int warp = threadIdx.x >> 5, lane = threadIdx.x & 31;
    const int tok = blockIdx.x * AT_WARPS + warp;
    float* sq = sm + warp * WSTRIDE;
    float* sk = sq + 16 * ROWP;
    float* sv = sk + 16 * ROWP;
    float* sw = sv + 16 * ROWP;
    const size_t base = (size_t)tok * 1024;

#pragma unroll
    for (int i = 0; i < 8; i++) {
        int idx = lane + i * 32;
        int row = idx >> 4, col = (idx & 15) * 4;
        *(float4*)&sq[row * ROWP + col] = *(const float4*)&qg[base + row * 64 + col];
        *(float4*)&sk[row * ROWP + col] = *(const float4*)&kg[base + row * 64 + col];
        *(float4*)&sv[row * ROWP + col] = *(const float4*)&vg[base + row * 64 + col];
    }
    __syncwarp();

    const int h = lane >> 1, gs = (lane & 1) * 8;
    float s[8];
#pragma unroll
    for (int gi = 0; gi < 8; gi++) s[gi] = 0.f;

#pragma unroll
    for (int dc = 0; dc < 4; dc++) {
        const float* qp = &sq[h * ROWP + dc * 16];
        float4 q0 = *(const float4*)(qp + 0);
        float4 q1 = *(const float4*)(qp + 4);
        float4 q2 = *(const float4*)(qp + 8);
        float4 q3 = *(const float4*)(qp + 12);
#pragma unroll
        for (int gi = 0; gi < 8; gi++) {
            const float* kp = &sk[(gs + gi) * ROWP + dc * 16];
            float4 k0 = *(const float4*)(kp + 0);
            float4 k1 = *(const float4*)(kp + 4);
            float4 k2 = *(const float4*)(kp + 8);
            float4 k3 = *(const float4*)(kp + 12);
            s[gi] += q0.x * k0.x + q0.y * k0.y + q0.z * k0.z + q0.w * k0.w
                   + q1.x * k1.x + q1.y * k1.y + q1.z * k1.z + q1.w * k1.w
                   + q2.x * k2.x + q2.y * k2.y + q2.z * k2.z + q2.w * k2.w
                   + q3.x * k3.x + q3.y * k3.y + q3.z * k3.z + q3.w * k3.w;
        }
    }

    const float* mp = mg + (size_t)tok * 256 + h * 16 + gs;
    float mx = -1e30f;
#pragma unroll
    for (int gi = 0; gi < 8; gi++) {
        s[gi] = s[gi] * 0.125f - 1e9f * mp[gi];
        mx = fmaxf(mx, s[gi]);
    }
    mx = fmaxf(mx, __shfl_xor_sync(0xffffffffu, mx, 1));
    float sum = 0.f;
#pragma unroll
    for (int gi = 0; gi < 8; gi++) { s[gi] = expf(s[gi] - mx); sum += s[gi]; }
    sum += __shfl_xor_sync(0xffffffffu, sum, 1);
    const float inv = 1.0f / sum;
#pragma unroll
    for (int gi = 0; gi < 8; gi++) sw[h * 17 + gs + gi] = s[gi] * inv;
    __syncwarp();

    const int dh = (lane & 1) * 32;
    float4 o[8];
#pragma unroll
    for (int j = 0; j < 8; j++) o[j] = make_float4(0.f, 0.f, 0.f, 0.f);
#pragma unroll
    for (int g = 0; g < 16; g++) {
        const float w = sw[h * 17 + g];
        const float* vp = &sv[g * ROWP + dh];
#pragma unroll
        for (int j = 0; j < 8; j++) {
            float4 vv = *(const float4*)&vp[j * 4];
            o[j].x += w * vv.x; o[j].y += w * vv.y;
            o[j].z += w * vv.z; o[j].w += w * vv.w;
        }
    }
    __syncwarp();

#pragma unroll
    for (int j = 0; j < 8; j++) *(float4*)&sq[h * 64 + dh + j * 4] = o[j];
    __syncwarp();
    float* op = outg + base;
#pragma unroll
    for (int i = 0; i < 8; i++) {
        int idx = lane + i * 32;
        *(float4*)&op[idx * 4] = *(const float4*)&sq[idx * 4];
    }
}

// ---------------- launch ----------------
extern "C" void kernel_launch(void* const* d_in, const int* in_sizes, int n_in,
                              void* d_out, int out_size)
{
    const float* Q  = (const float*)d_in[0];
    const float* K  = (const float*)d_in[1];
    const float* V  = (const float*)d_in[2];
    const float* Msk= (const float*)d_in[3];
    const float* Wq = (const float*)d_in[4];
    const float* bq = (const float*)d_in[5];
    const float* Wk = (const float*)d_in[6];
    const float* bk = (const float*)d_in[7];
    const float* Wv = (const float*)d_in[8];
    const float* bv = (const float*)d_in[9];
    const float* Wo = (const float*)d_in[10];
    const float* bo = (const float*)d_in[11];
    float* out = (float*)d_out;

    float *gq, *gk, *gv, *ga, *gwtf;
    cudaGetSymbolAddress((void**)&gq, g_q);
    cudaGetSymbolAddress((void**)&gk, g_k);
    cudaGetSymbolAddress((void**)&gv, g_v);
    cudaGetSymbolAddress((void**)&ga, g_attn);
    cudaGetSymbolAddress((void**)&gwtf, g_wtf);

    cudaFuncSetAttribute(gemm_qkv, cudaFuncAttributeMaxDynamicSharedMemorySize, GEMM_SMEM);
    cudaFuncSetAttribute(gemm_out, cudaFuncAttributeMaxDynamicSharedMemorySize, GEMM_SMEM);

    // 1. transpose weights (f32), 2. pack weights + activations to fp16 frags
    wtrans<<<dim3(32, 32, 4), dim3(32, 8)>>>(Wq, Wk, Wv, Wo, gwtf);
    apack_w<<<dim3(NT, NDIM / 128, 4), 256>>>();
    apack_qkv<<<dim3(NT, MDIM / 128, 3), 256>>>(Q, K, V);

    // 3. QKV projections (fp16 tensor cores)
    dim3 gg(NDIM / BN, MDIM / BM, 3);   // (8, 128, 3)
    gemm_qkv<<<gg, 256, GEMM_SMEM>>>(bq, bk, bv, gq, gk, gv);

    // 4. per-token attention over heads
    attn_kernel<<<MDIM / AT_WARPS, AT_WARPS * 32>>>(gq, gk, gv, Msk, ga);

    // 5. pack attn output, 6. output projection
    apack_attn<<<dim3(NT, MDIM / 128), 256>>>(ga);
    float* out2 = ((long long)out_size >= 2LL * MDIM * NDIM) ? out + (size_t)MDIM * NDIM
                                                             : nullptr;
    dim3 go(NDIM / BN, MDIM / BM);
    gemm_out<<<go, 256, GEMM_SMEM>>>(bo, out, out2);
}

// round 5
// speedup vs baseline: 2.2900x; 1.0376x over previous
#include <cuda_runtime.h>
#include <cuda_fp16.h>
#include <cstdint>

// ---------------- problem dims ----------------
#define MDIM 16384   // B*S
#define NDIM 1024    // DM
#define KDIM 1024    // DM

// ---------------- GEMM tiling ----------------
#define BM 128
#define BN 128
#define BK 64
#define NT (KDIM / BK)              // 16 k-stages
#define A_STAGE 16384               // 128x64 fp16
#define B_STAGE 16384               // 128x64 fp16
#define STAGE_BYTES (A_STAGE + B_STAGE)   // 32KB
#define GEMM_SMEM (3 * STAGE_BYTES)       // 96KB

// packed sizes (uint4 units)
#define ACT_CHUNKS ((MDIM / 128) * NT)    // 128*16 chunks per activation matrix
#define W_CHUNKS   ((NDIM / 128) * NT)    // 8*16 per weight matrix
#define CHUNK_U4   1024                   // 16KB per chunk
#define ACT_PACK_U4 ((size_t)ACT_CHUNKS * CHUNK_U4)
#define W_PACK_U4   ((size_t)W_CHUNKS * CHUNK_U4)

// ---------------- scratch (no allocs allowed) ----------------
__device__ float g_q[(size_t)MDIM * NDIM];
__device__ float g_k[(size_t)MDIM * NDIM];
__device__ float g_v[(size_t)MDIM * NDIM];
__device__ float g_attn[(size_t)MDIM * NDIM];
__device__ float g_wtf[4ull * NDIM * KDIM];            // f32 transposed weights
__device__ uint4 g_wp[4ull * W_PACK_U4];               // packed fp16 weights
__device__ uint4 g_qp[ACT_PACK_U4];
__device__ uint4 g_kp[ACT_PACK_U4];
__device__ uint4 g_vp[ACT_PACK_U4];
__device__ uint4 g_ap[ACT_PACK_U4];                    // packed attn output

// ---------------- helpers ----------------
__device__ __forceinline__ uint32_t smem_u32(const void* p) {
    uint32_t a;
    asm("{ .reg .u64 t; cvta.to.shared.u64 t, %1; cvt.u32.u64 %0, t; }" : "=r"(a) : "l"(p));
    return a;
}

__device__ __forceinline__ void cp_async16(uint32_t saddr, const void* gaddr) {
    asm volatile("cp.async.cg.shared.global [%0], [%1], 16;\n" :: "r"(saddr), "l"(gaddr));
}

__device__ __forceinline__ void lds128(uint32_t& a, uint32_t& b, uint32_t& c, uint32_t& d,
                                       uint32_t addr) {
    asm volatile("ld.shared.v4.b32 {%0,%1,%2,%3}, [%4];"
                 : "=r"(a), "=r"(b), "=r"(c), "=r"(d) : "r"(addr));
}

__device__ __forceinline__ void mma_f16(float c[4], const uint32_t a[4],
                                        uint32_t b0, uint32_t b1) {
    asm volatile(
        "mma.sync.aligned.m16n8k16.row.col.f32.f16.f16.f32 "
        "{%0,%1,%2,%3}, {%4,%5,%6,%7}, {%8,%9}, {%0,%1,%2,%3};\n"
        : "+f"(c[0]), "+f"(c[1]), "+f"(c[2]), "+f"(c[3])
        : "r"(a[0]), "r"(a[1]), "r"(a[2]), "r"(a[3]), "r"(b0), "r"(b1));
}

__device__ __forceinline__ uint32_t ph2(float lo, float hi) {
    __half2 h = __floats2half2_rn(lo, hi);
    return *reinterpret_cast<uint32_t*>(&h);
}

// ---------------- weight transpose: Wt[n][k] = W[k][n] ----------------
__global__ void wtrans(const float* __restrict__ W0, const float* __restrict__ W1,
                       const float* __restrict__ W2, const float* __restrict__ W3,
                       float* __restrict__ out)
{
    __shared__ float t[32][33];
    const float* W = (blockIdx.z == 0) ? W0 : (blockIdx.z == 1) ? W1
                   : (blockIdx.z == 2) ? W2 : W3;
    float* O = out + (size_t)blockIdx.z * NDIM * KDIM;
    const int n0 = blockIdx.x * 32, k0 = blockIdx.y * 32;
    const int tx = threadIdx.x, ty = threadIdx.y;   // 32 x 8
#pragma unroll
    for (int i = 0; i < 4; i++)
        t[ty + 8 * i][tx] = W[(size_t)(k0 + ty + 8 * i) * NDIM + n0 + tx];
    __syncthreads();
#pragma unroll
    for (int i = 0; i < 4; i++)
        O[(size_t)(n0 + ty + 8 * i) * KDIM + k0 + tx] = t[tx][ty + 8 * i];
}

// ---------------- fragment pack: f32 row-major [R x 1024] -> fp16 mma frags ----------
// chunk (mblk, kt): 128 rows x 64 k, 16KB. Within chunk: [kstep(4)][b(8)][lane(32)] x 16B
// slot words: {X[r][k..k+1], X[r+8][k..k+1], X[r][k+8..k+9], X[r+8][k+8..k+9]} fp16x2
// with r = b*16 + grp, k = kstep*16 + 2*tig, (grp,tig) = (lane>>2, lane&3).
__device__ __forceinline__ void apack_body(const float* __restrict__ src,
                                           uint4* __restrict__ dst)
{
    __shared__ float s[128 * 68];
    const int t = threadIdx.x;                 // 256
    const int mblk = blockIdx.y, kt = blockIdx.x;
#pragma unroll
    for (int i = 0; i < 8; i++) {
        int idx = t + i * 256;
        int row = idx >> 4, c4 = (idx & 15) * 4;
        *(float4*)&s[row * 68 + c4] =
            *(const float4*)&src[(size_t)(mblk * 128 + row) * KDIM + kt * 64 + c4];
    }
    __syncthreads();
    const int b = t >> 5, l = t & 31, grp = l >> 2, tig = l & 3;
    const int r0 = (b * 16 + grp) * 68, r1 = r0 + 8 * 68;
    uint4* base = dst + ((size_t)(mblk * NT + kt)) * CHUNK_U4 + b * 32 + l;
#pragma unroll
    for (int ks = 0; ks < 4; ks++) {
        const int c = ks * 16 + 2 * tig;
        float2 x0 = *(const float2*)&s[r0 + c];
        float2 x1 = *(const float2*)&s[r1 + c];
        float2 x2 = *(const float2*)&s[r0 + c + 8];
        float2 x3 = *(const float2*)&s[r1 + c + 8];
        uint4 o;
        o.x = ph2(x0.x, x0.y);
        o.y = ph2(x1.x, x1.y);
        o.z = ph2(x2.x, x2.y);
        o.w = ph2(x3.x, x3.y);
        base[ks * 256] = o;
    }
}

__global__ void apack_qkv(const float* __restrict__ Q, const float* __restrict__ K,
                          const float* __restrict__ V)
{
    const int z = blockIdx.z;
    apack_body(z == 0 ? Q : z == 1 ? K : V,
               z == 0 ? g_qp : z == 1 ? g_kp : g_vp);
}

__global__ void apack_w()
{
    const int z = blockIdx.z;
    apack_body(g_wtf + (size_t)z * NDIM * KDIM, g_wp + (size_t)z * W_PACK_U4);
}

__global__ void apack_attn(const float* __restrict__ A) { apack_body(A, g_ap); }

// ---------------- fp16 tensor-core GEMM (all operands pre-packed) ----------------
// C[M,N] = A @ Wt^T + bias. 128x128 CTA tile, 8 warps (2x4), warp tile 64x32.
// Single barrier per k-stage; fragment registers double-buffered across ks steps.
__device__ __forceinline__ void gemm_body(const uint4* __restrict__ Ap,
                                          const uint4* __restrict__ Bp,
                                          const float* __restrict__ bias,
                                          float* __restrict__ C, float* __restrict__ C2,
                                          uint32_t sb)
{
    const int tid = threadIdx.x;               // 256
    const int wid = tid >> 5, lane = tid & 31;
    const int grp = lane >> 2, tig = lane & 3;
    const int warp_m = wid >> 2, warp_n = wid & 3;
    const int mblk = blockIdx.y, nblk = blockIdx.x;

    float acc[4][4][4];
#pragma unroll
    for (int mi = 0; mi < 4; mi++)
#pragma unroll
        for (int ni = 0; ni < 4; ni++)
#pragma unroll
            for (int r = 0; r < 4; r++) acc[mi][ni][r] = 0.f;

    const uint4* Abase = Ap + (size_t)mblk * NT * CHUNK_U4 + tid * 4;
    const uint4* Bbase = Bp + (size_t)nblk * NT * CHUNK_U4 + tid * 4;

    auto stage_in = [&](int kt, int slot) {
        const uint32_t da = sb + slot * STAGE_BYTES + tid * 64;
        const uint32_t db = da + A_STAGE;
        const uint4* sa = Abase + (size_t)kt * CHUNK_U4;
        const uint4* sbp = Bbase + (size_t)kt * CHUNK_U4;
#pragma unroll
        for (int i = 0; i < 4; i++) cp_async16(da + i * 16, sa + i);
#pragma unroll
        for (int i = 0; i < 4; i++) cp_async16(db + i * 16, sbp + i);
        asm volatile("cp.async.commit_group;\n");
    };

    stage_in(0, 0);
    stage_in(1, 1);

    const uint32_t aOff = warp_m * 2048 + lane * 16;
    const uint32_t bOff = A_STAGE + warp_n * 1024 + lane * 16;

    uint32_t a4[2][4][4], b4[2][2][4];

    int slot = 0;
    for (int kt = 0; kt < NT; kt++) {
        if (kt < NT - 1) asm volatile("cp.async.wait_group 1;\n");
        else             asm volatile("cp.async.wait_group 0;\n");
        __syncthreads();

        const uint32_t aBase = sb + slot * STAGE_BYTES + aOff;
        const uint32_t bBase = sb + slot * STAGE_BYTES + bOff;

        // preload ks=0 fragments into buffer 0
#pragma unroll
        for (int mi = 0; mi < 4; mi++)
            lds128(a4[0][mi][0], a4[0][mi][1], a4[0][mi][2], a4[0][mi][3],
                   aBase + mi * 512);
#pragma unroll
        for (int np = 0; np < 2; np++)
            lds128(b4[0][np][0], b4[0][np][1], b4[0][np][2], b4[0][np][3],
                   bBase + np * 512);

        // kick off the next-next stage's async copies while mma runs
        if (kt + 2 < NT) {
            int sl2 = slot + 2; if (sl2 >= 3) sl2 -= 3;
            stage_in(kt + 2, sl2);
        }

#pragma unroll
        for (int ks = 0; ks < 4; ks++) {
            const int cur = ks & 1, nxt = cur ^ 1;
            if (ks < 3) {
#pragma unroll
                for (int mi = 0; mi < 4; mi++)
                    lds128(a4[nxt][mi][0], a4[nxt][mi][1], a4[nxt][mi][2], a4[nxt][mi][3],
                           aBase + (ks + 1) * 4096 + mi * 512);
#pragma unroll
                for (int np = 0; np < 2; np++)
                    lds128(b4[nxt][np][0], b4[nxt][np][1], b4[nxt][np][2], b4[nxt][np][3],
                           bBase + (ks + 1) * 4096 + np * 512);
            }
#pragma unroll
            for (int mi = 0; mi < 4; mi++) {
#pragma unroll
                for (int np = 0; np < 2; np++) {
                    mma_f16(acc[mi][np * 2 + 0], a4[cur][mi], b4[cur][np][0], b4[cur][np][2]);
                    mma_f16(acc[mi][np * 2 + 1], a4[cur][mi], b4[cur][np][1], b4[cur][np][3]);
                }
            }
        }
        slot++; if (slot >= 3) slot -= 3;
    }

    // ---- epilogue: +bias, store (optionally duplicated) ----
    const int n0 = nblk * BN + warp_n * 32;
    const int m0 = mblk * BM + warp_m * 64;
#pragma unroll
    for (int mi = 0; mi < 4; mi++) {
        const int r0 = m0 + mi * 16 + grp;
#pragma unroll
        for (int ni = 0; ni < 4; ni++) {
            const int col = n0 + (ni >> 1) * 16 + (ni & 1) * 8 + tig * 2;
            float2 bv = *(const float2*)&bias[col];
            float2 lo = make_float2(acc[mi][ni][0] + bv.x, acc[mi][ni][1] + bv.y);
            float2 hi = make_float2(acc[mi][ni][2] + bv.x, acc[mi][ni][3] + bv.y);
            *(float2*)&C[(size_t)r0 * NDIM + col] = lo;
            *(float2*)&C[(size_t)(r0 + 8) * NDIM + col] = hi;
            if (C2) {
                *(float2*)&C2[(size_t)r0 * NDIM + col] = lo;
                *(float2*)&C2[(size_t)(r0 + 8) * NDIM + col] = hi;
            }
        }
    }
}

__global__ void __launch_bounds__(256, 2) gemm_qkv(
    const float* __restrict__ bq, const float* __restrict__ bk, const float* __restrict__ bv,
    float* __restrict__ Cq, float* __restrict__ Ck, float* __restrict__ Cv)
{
    extern __shared__ char smem[];
    const int z = blockIdx.z;
    gemm_body(z == 0 ? g_qp : z == 1 ? g_kp : g_vp,
              g_wp + (size_t)z * W_PACK_U4,
              z == 0 ? bq : z == 1 ? bk : bv,
              z == 0 ? Cq : z == 1 ? Ck : Cv, nullptr, smem_u32(smem));
}

__global__ void __launch_bounds__(256, 2) gemm_out(
    const float* __restrict__ bias, float* __restrict__ C, float* __restrict__ C2)
{
    extern __shared__ char smem[];
    gemm_body(g_ap, g_wp + 3ull * W_PACK_U4, bias, C, C2, smem_u32(smem));
}

// ---------------- per-token head-axis attention (unchanged, known-good) ----------------
#define AT_WARPS 2
#define ROWP 68
#define WSTRIDE (3 * 16 * ROWP + 16 * 17)

__global__ void attn_kernel(const float* __restrict__ qg, const float* __restrict__ kg,
                            const float* __restrict__ vg, const float* __restrict__ mg,
                            float* __restrict__ outg)
{
    __shared__ float sm[AT_WARPS * WSTRIDE];
    const int warp = threadIdx.x >> 5, lane = threadIdx.x & 31;
    const int tok = blockIdx.x * AT_WARPS + warp;
    float* sq = sm + warp * WSTRIDE;
    float* sk = sq + 16 * ROWP;
    float* sv = sk + 16 * ROWP;
    float* sw = sv + 16 * ROWP;
    const size_t base = (size_t)tok * 1024;

#pragma unroll
    for (int i = 0; i < 8; i++) {
        int idx = lane + i * 32;
        int row = idx >> 4, col = (idx & 15) * 4;
        *(float4*)&sq[row * ROWP + col] = *(const float4*)&qg[base + row * 64 + col];
        *(float4*)&sk[row * ROWP + col] = *(const float4*)&kg[base + row * 64 + col];
        *(float4*)&sv[row * ROWP + col] = *(const float4*)&vg[base + row * 64 + col];
    }
    __syncwarp();

    const int h = lane >> 1, gs = (lane & 1) * 8;
    float s[8];
#pragma unroll
    for (int gi = 0; gi < 8; gi++) s[gi] = 0.f;

#pragma unroll
    for (int dc = 0; dc < 4; dc++) {
        const float* qp = &sq[h * ROWP + dc * 16];
        float4 q0 = *(const float4*)(qp + 0);
        float4 q1 = *(const float4*)(qp + 4);
        float4 q2 = *(const float4*)(qp + 8);
        float4 q3 = *(const float4*)(qp + 12);
#pragma unroll
        for (int gi = 0; gi < 8; gi++) {
            const float* kp = &sk[(gs + gi) * ROWP + dc * 16];
            float4 k0 = *(const float4*)(kp + 0);
            float4 k1 = *(const float4*)(kp + 4);
            float4 k2 = *(const float4*)(kp + 8);
            float4 k3 = *(const float4*)(kp + 12);
            s[gi] += q0.x * k0.x + q0.y * k0.y + q0.z * k0.z + q0.w * k0.w
                   + q1.x * k1.x + q1.y * k1.y + q1.z * k1.z + q1.w * k1.w
                   + q2.x * k2.x + q2.y * k2.y + q2.z * k2.z + q2.w * k2.w
                   + q3.x * k3.x + q3.y * k3.y + q3.z * k3.z + q3.w * k3.w;
        }
    }

    const float* mp = mg + (size_t)tok * 256 + h * 16 + gs;
    float mx = -1e30f;
#pragma unroll
    for (int gi = 0; gi < 8; gi++) {
        s[gi] = s[gi] * 0.125f - 1e9f * mp[gi];
        mx = fmaxf(mx, s[gi]);
    }
    mx = fmaxf(mx, __shfl_xor_sync(0xffffffffu, mx, 1));
    float sum = 0.f;
#pragma unroll
    for (int gi = 0; gi < 8; gi++) { s[gi] = expf(s[gi] - mx); sum += s[gi]; }
    sum += __shfl_xor_sync(0xffffffffu, sum, 1);
    const float inv = 1.0f / sum;
#pragma unroll
    for (int gi = 0; gi < 8; gi++) sw[h * 17 + gs + gi] = s[gi] * inv;
    __syncwarp();

    const int dh = (lane & 1) * 32;
    float4 o[8];
#pragma unroll
    for (int j = 0; j < 8; j++) o[j] = make_float4(0.f, 0.f, 0.f, 0.f);
#pragma unroll
    for (int g = 0; g < 16; g++) {
        const float w = sw[h * 17 + g];
        const float* vp = &sv[g * ROWP + dh];
#pragma unroll
        for (int j = 0; j < 8; j++) {
            float4 vv = *(const float4*)&vp[j * 4];
            o[j].x += w * vv.x; o[j].y += w * vv.y;
            o[j].z += w * vv.z; o[j].w += w * vv.w;
        }
    }
    __syncwarp();

#pragma unroll
    for (int j = 0; j < 8; j++) *(float4*)&sq[h * 64 + dh + j * 4] = o[j];
    __syncwarp();
    float* op = outg + base;
#pragma unroll
    for (int i = 0; i < 8; i++) {
        int idx = lane + i * 32;
        *(float4*)&op[idx * 4] = *(const float4*)&sq[idx * 4];
    }
}

// ---------------- launch ----------------
extern "C" void kernel_launch(void* const* d_in, const int* in_sizes, int n_in,
                              void* d_out, int out_size)
{
    const float* Q  = (const float*)d_in[0];
    const float* K  = (const float*)d_in[1];
    const float* V  = (const float*)d_in[2];
    const float* Msk= (const float*)d_in[3];
    const float* Wq = (const float*)d_in[4];
    const float* bq = (const float*)d_in[5];
    const float* Wk = (const float*)d_in[6];
    const float* bk = (const float*)d_in[7];
    const float* Wv = (const float*)d_in[8];
    const float* bv = (const float*)d_in[9];
    const float* Wo = (const float*)d_in[10];
    const float* bo = (const float*)d_in[11];
    float* out = (float*)d_out;

    float *gq, *gk, *gv, *ga, *gwtf;
    cudaGetSymbolAddress((void**)&gq, g_q);
    cudaGetSymbolAddress((void**)&gk, g_k);
    cudaGetSymbolAddress((void**)&gv, g_v);
    cudaGetSymbolAddress((void**)&ga, g_attn);
    cudaGetSymbolAddress((void**)&gwtf, g_wtf);

    cudaFuncSetAttribute(gemm_qkv, cudaFuncAttributeMaxDynamicSharedMemorySize, GEMM_SMEM);
    cudaFuncSetAttribute(gemm_out, cudaFuncAttributeMaxDynamicSharedMemorySize, GEMM_SMEM);

    // 1. transpose weights (f32), 2. pack weights + activations to fp16 frags
    wtrans<<<dim3(32, 32, 4), dim3(32, 8)>>>(Wq, Wk, Wv, Wo, gwtf);
    apack_w<<<dim3(NT, NDIM / 128, 4), 256>>>();
    apack_qkv<<<dim3(NT, MDIM / 128, 3), 256>>>(Q, K, V);

    // 3. QKV projections (fp16 tensor cores)
    dim3 gg(NDIM / BN, MDIM / BM, 3);   // (8, 128, 3)
    gemm_qkv<<<gg, 256, GEMM_SMEM>>>(bq, bk, bv, gq, gk, gv);

    // 4. per-token attention over heads
    attn_kernel<<<MDIM / AT_WARPS, AT_WARPS * 32>>>(gq, gk, gv, Msk, ga);

    // 5. pack attn output, 6. output projection
    apack_attn<<<dim3(NT, MDIM / 128), 256>>>(ga);
    float* out2 = ((long long)out_size >= 2LL * MDIM * NDIM) ? out + (size_t)MDIM * NDIM
                                                             : nullptr;
    dim3 go(NDIM / BN, MDIM / BM);
    gemm_out<<<go, 256, GEMM_SMEM>>>(bo, out, out2);
}